// round 1
// baseline (speedup 1.0000x reference)
#include <cuda_runtime.h>

// ---------------------------------------------------------------------------
// M1_17008070492428: batched tiny Hopfield attention + classifier head.
//   B=131072 samples, each (S=14, D=16) -> (7,) softmax probs.
//
// Algebra:
//   xhat = LN(x) (shared by q/k/v since input identical, affine differs)
//   Q = xhat @ (Wq*g_q)^T + bqEff      (bqEff = bq + Wq@beta_q)
//   A = softmax(Q K^T), O = A V
//   t[d] = sum_s Wm[s] * O[s,d]
//   z[c] = sum_d M[c,d]*t[d] + ez[c],  M = Wb@Wo,
//   ez[c] = bb[c] + sum_o Wb[c,o]*(c0*bo[o]+bm),  c0 = sum_s Wm[s]
//   out = softmax(z)
// ---------------------------------------------------------------------------

typedef unsigned long long u64;

#define LN_EPS 1e-5f
constexpr int ROWW = 20;    // padded row stride (floats) for smem tiles
constexpr int GW   = 1136;  // per-group smem words (1136 % 32 == 16 -> two
                            // warp-halves hit disjoint bank halves)

__device__ __forceinline__ u64 ffma2(u64 a, u64 b, u64 c) {
    u64 d;
    asm("fma.rn.f32x2 %0, %1, %2, %3;" : "=l"(d) : "l"(a), "l"(b), "l"(c));
    return d;
}
__device__ __forceinline__ u64 fmul2(u64 a, u64 b) {
    u64 d;
    asm("mul.rn.f32x2 %0, %1, %2;" : "=l"(d) : "l"(a), "l"(b));
    return d;
}
__device__ __forceinline__ u64 pack2(float lo, float hi) {
    u64 r;
    asm("mov.b64 %0, {%1, %2};" : "=l"(r) : "f"(lo), "f"(hi));
    return r;
}
__device__ __forceinline__ float hsum2(u64 v) {
    float lo, hi;
    asm("mov.b64 {%0, %1}, %2;" : "=f"(lo), "=f"(hi) : "l"(v));
    return lo + hi;
}

struct __align__(16) Params {
    float wq[16][16], wk[16][16], wv[16][16];  // LN-gamma folded in
    float bq[16], bk[16], bv[16];              // LN-beta folded in
    float M[7][16];                            // Wb @ Wo
    float ez[8];
    float wm[16];                              // Wm padded with zeros
};
__device__ Params g_P;

__global__ void setup_kernel(
    const float* __restrict__ lnqg, const float* __restrict__ lnqb,
    const float* __restrict__ lnkg, const float* __restrict__ lnkb,
    const float* __restrict__ lnvg, const float* __restrict__ lnvb,
    const float* __restrict__ Wq,  const float* __restrict__ bq,
    const float* __restrict__ Wk,  const float* __restrict__ bk,
    const float* __restrict__ Wv,  const float* __restrict__ bv,
    const float* __restrict__ Wo,  const float* __restrict__ bo,
    const float* __restrict__ Wm,  const float* __restrict__ bm,
    const float* __restrict__ Wb,  const float* __restrict__ bb)
{
    const int t = threadIdx.x;           // 256 threads, 1 block
    const int e = t >> 4, d = t & 15;
    g_P.wq[e][d] = Wq[e * 16 + d] * lnqg[d];
    g_P.wk[e][d] = Wk[e * 16 + d] * lnkg[d];
    g_P.wv[e][d] = Wv[e * 16 + d] * lnvg[d];
    if (t < 16) {
        float aq = bq[t], ak = bk[t], av = bv[t];
        #pragma unroll
        for (int i = 0; i < 16; i++) {
            aq = fmaf(lnqb[i], Wq[t * 16 + i], aq);
            ak = fmaf(lnkb[i], Wk[t * 16 + i], ak);
            av = fmaf(lnvb[i], Wv[t * 16 + i], av);
        }
        g_P.bq[t] = aq; g_P.bk[t] = ak; g_P.bv[t] = av;
        g_P.wm[t] = (t < 14) ? Wm[t] : 0.f;
    }
    if (t < 112) {
        const int c = t >> 4, dd = t & 15;
        float s = 0.f;
        for (int o = 0; o < 128; o++)
            s = fmaf(Wb[c * 128 + o], Wo[o * 16 + dd], s);
        g_P.M[c][dd] = s;
    }
    if (t >= 112 && t < 119) {
        const int c = t - 112;
        float c0 = 0.f;
        for (int s = 0; s < 14; s++) c0 += Wm[s];
        float z = bb[c];
        const float bmv = bm[0];
        for (int o = 0; o < 128; o++)
            z = fmaf(Wb[c * 128 + o], fmaf(c0, bo[o], bmv), z);
        g_P.ez[c] = z;
    }
    if (t == 119) g_P.ez[7] = 0.f;
}

__global__ __launch_bounds__(128, 4) void hopfield_kernel(
    const float* __restrict__ x, float* __restrict__ out, int nB)
{
    __shared__ __align__(16) float sm[8 * GW];
    const int tid  = threadIdx.x;
    const int lane = tid & 31;
    const int t    = lane & 15;                   // lane within sample group
    const int g    = ((tid >> 5) << 1) | (lane >> 4);  // group 0..7 in block

    float* S  = sm + g * GW;
    float* XH = S;            // 14 x ROWW : input tile / xhat / weighted-O
    float* Qb = S + 280;      // 14 x ROWW
    float* Kb = S + 560;
    float* Vb = S + 840;
    float* Tb = S + 1120;     // 16 : t-vector

    // per-lane cached weights (column e = t of each projection)
    u64 wq[8], wk[8], wv[8];
    {
        const ulonglong2* pq = (const ulonglong2*)g_P.wq[t];
        const ulonglong2* pk = (const ulonglong2*)g_P.wk[t];
        const ulonglong2* pv = (const ulonglong2*)g_P.wv[t];
        #pragma unroll
        for (int i = 0; i < 4; i++) {
            ulonglong2 a = pq[i]; wq[2 * i] = a.x; wq[2 * i + 1] = a.y;
            ulonglong2 b = pk[i]; wk[2 * i] = b.x; wk[2 * i + 1] = b.y;
            ulonglong2 c = pv[i]; wv[2 * i] = c.x; wv[2 * i + 1] = c.y;
        }
    }
    const float bqe = g_P.bq[t], bke = g_P.bk[t], bve = g_P.bv[t];
    const float wmq = g_P.wm[t];   // 0 for t >= 14

    for (long long samp = (long long)blockIdx.x * 8 + g; samp < nB;
         samp += (long long)gridDim.x * 8)
    {
        // ------- load sample tile (coalesced float4) -------
        const float4* gp = (const float4*)(x + samp * 224);
        #pragma unroll
        for (int j = 0; j < 4; j++) {
            int i = t + j * 16;
            if (i < 56) {
                float4 v = __ldg(gp + i);
                *(float4*)&XH[(i >> 2) * ROWW + ((i & 3) << 2)] = v;
            }
        }
        __syncwarp();

        // ------- LayerNorm (row per lane), write xhat in place -------
        if (t < 14) {
            float* row = &XH[t * ROWW];
            float4 a = ((const float4*)row)[0];
            float4 b = ((const float4*)row)[1];
            float4 c = ((const float4*)row)[2];
            float4 d = ((const float4*)row)[3];
            float s1 = ((a.x + a.y) + (a.z + a.w)) + ((b.x + b.y) + (b.z + b.w))
                     + ((c.x + c.y) + (c.z + c.w)) + ((d.x + d.y) + (d.z + d.w));
            float s2 = a.x * a.x;
            s2 = fmaf(a.y, a.y, s2); s2 = fmaf(a.z, a.z, s2); s2 = fmaf(a.w, a.w, s2);
            s2 = fmaf(b.x, b.x, s2); s2 = fmaf(b.y, b.y, s2); s2 = fmaf(b.z, b.z, s2); s2 = fmaf(b.w, b.w, s2);
            s2 = fmaf(c.x, c.x, s2); s2 = fmaf(c.y, c.y, s2); s2 = fmaf(c.z, c.z, s2); s2 = fmaf(c.w, c.w, s2);
            s2 = fmaf(d.x, d.x, s2); s2 = fmaf(d.y, d.y, s2); s2 = fmaf(d.z, d.z, s2); s2 = fmaf(d.w, d.w, s2);
            const float m   = s1 * 0.0625f;
            const float var = fmaf(-m, m, s2 * 0.0625f);
            const float rs  = rsqrtf(var + LN_EPS);
            a.x = (a.x - m) * rs; a.y = (a.y - m) * rs; a.z = (a.z - m) * rs; a.w = (a.w - m) * rs;
            b.x = (b.x - m) * rs; b.y = (b.y - m) * rs; b.z = (b.z - m) * rs; b.w = (b.w - m) * rs;
            c.x = (c.x - m) * rs; c.y = (c.y - m) * rs; c.z = (c.z - m) * rs; c.w = (c.w - m) * rs;
            d.x = (d.x - m) * rs; d.y = (d.y - m) * rs; d.z = (d.z - m) * rs; d.w = (d.w - m) * rs;
            ((float4*)row)[0] = a; ((float4*)row)[1] = b;
            ((float4*)row)[2] = c; ((float4*)row)[3] = d;
        }
        __syncwarp();

        // ------- QKV projection (column e = t per lane), packed f32x2 -------
        #pragma unroll
        for (int s = 0; s < 14; s++) {
            const ulonglong2* xr = (const ulonglong2*)&XH[s * ROWW];
            u64 aQ = 0ull, aK = 0ull, aV = 0ull;
            #pragma unroll
            for (int i = 0; i < 4; i++) {
                ulonglong2 xp = xr[i];            // broadcast within group
                aQ = ffma2(xp.x, wq[2 * i], aQ); aQ = ffma2(xp.y, wq[2 * i + 1], aQ);
                aK = ffma2(xp.x, wk[2 * i], aK); aK = ffma2(xp.y, wk[2 * i + 1], aK);
                aV = ffma2(xp.x, wv[2 * i], aV); aV = ffma2(xp.y, wv[2 * i + 1], aV);
            }
            Qb[s * ROWW + t] = hsum2(aQ) + bqe;
            Kb[s * ROWW + t] = hsum2(aK) + bke;
            Vb[s * ROWW + t] = hsum2(aV) + bve;
        }
        __syncwarp();

        // ------- attention row q = t : scores, softmax, O row -------
        if (t < 14) {
            u64 qr[8];
            {
                const ulonglong2* q2 = (const ulonglong2*)&Qb[t * ROWW];
                #pragma unroll
                for (int i = 0; i < 4; i++) {
                    ulonglong2 v = q2[i]; qr[2 * i] = v.x; qr[2 * i + 1] = v.y;
                }
            }
            float sc[14];
            float mx = -1e30f;
            #pragma unroll
            for (int k = 0; k < 14; k++) {
                const ulonglong2* kr = (const ulonglong2*)&Kb[k * ROWW];
                u64 a = 0ull;
                #pragma unroll
                for (int i = 0; i < 4; i++) {
                    ulonglong2 kp = kr[i];
                    a = ffma2(qr[2 * i], kp.x, a);
                    a = ffma2(qr[2 * i + 1], kp.y, a);
                }
                sc[k] = hsum2(a);
                mx = fmaxf(mx, sc[k]);
            }
            float ssum = 0.f;
            #pragma unroll
            for (int k = 0; k < 14; k++) { sc[k] = __expf(sc[k] - mx); ssum += sc[k]; }
            const float inv = __fdividef(1.f, ssum);

            u64 o[8] = {0ull, 0ull, 0ull, 0ull, 0ull, 0ull, 0ull, 0ull};
            #pragma unroll
            for (int k = 0; k < 14; k++) {
                const u64 a2 = pack2(sc[k], sc[k]);
                const ulonglong2* vr = (const ulonglong2*)&Vb[k * ROWW];
                #pragma unroll
                for (int i = 0; i < 4; i++) {
                    ulonglong2 vp = vr[i];
                    o[2 * i]     = ffma2(a2, vp.x, o[2 * i]);
                    o[2 * i + 1] = ffma2(a2, vp.y, o[2 * i + 1]);
                }
            }
            // fold softmax norm + Wm[q] into one scale; write weighted O row
            const float w  = wmq * inv;
            const u64  w2  = pack2(w, w);
            ulonglong2* orow = (ulonglong2*)&XH[t * ROWW];
            #pragma unroll
            for (int i = 0; i < 4; i++) {
                ulonglong2 st;
                st.x = fmul2(o[2 * i], w2);
                st.y = fmul2(o[2 * i + 1], w2);
                orow[i] = st;
            }
        }
        __syncwarp();

        // ------- t[d] = sum_s weightedO[s,d]  (column d = t per lane) -------
        float td = 0.f;
        #pragma unroll
        for (int s = 0; s < 14; s++) td += XH[s * ROWW + t];
        Tb[t] = td;
        __syncwarp();

        // ------- z = M @ t + ez ; softmax over 7 across lanes 0..6 -------
        float z = -1e30f;
        if (t < 7) {
            const ulonglong2* tv = (const ulonglong2*)Tb;
            const ulonglong2* pm = (const ulonglong2*)g_P.M[t];  // L1-resident
            u64 a = 0ull;
            #pragma unroll
            for (int i = 0; i < 4; i++) {
                ulonglong2 tp = tv[i];
                ulonglong2 mp = pm[i];
                a = ffma2(mp.x, tp.x, a);
                a = ffma2(mp.y, tp.y, a);
            }
            z = hsum2(a) + g_P.ez[t];
        }
        float m2 = z;
        m2 = fmaxf(m2, __shfl_xor_sync(0xffffffffu, m2, 4, 8));
        m2 = fmaxf(m2, __shfl_xor_sync(0xffffffffu, m2, 2, 8));
        m2 = fmaxf(m2, __shfl_xor_sync(0xffffffffu, m2, 1, 8));
        float exz = __expf(z - m2);
        float sz = exz;
        sz += __shfl_xor_sync(0xffffffffu, sz, 4, 8);
        sz += __shfl_xor_sync(0xffffffffu, sz, 2, 8);
        sz += __shfl_xor_sync(0xffffffffu, sz, 1, 8);
        if (t < 7) out[samp * 7 + t] = __fdividef(exz, sz);
    }
}

extern "C" void kernel_launch(void* const* d_in, const int* in_sizes, int n_in,
                              void* d_out, int out_size)
{
    const float* sample = (const float*)d_in[0];
    setup_kernel<<<1, 256>>>(
        (const float*)d_in[1],  (const float*)d_in[2],
        (const float*)d_in[3],  (const float*)d_in[4],
        (const float*)d_in[5],  (const float*)d_in[6],
        (const float*)d_in[7],  (const float*)d_in[8],
        (const float*)d_in[9],  (const float*)d_in[10],
        (const float*)d_in[11], (const float*)d_in[12],
        (const float*)d_in[13], (const float*)d_in[14],
        (const float*)d_in[15], (const float*)d_in[16],
        (const float*)d_in[17], (const float*)d_in[18]);

    const int nB = in_sizes[0] / 224;   // B = 131072
    hopfield_kernel<<<2048, 128>>>(sample, (float*)d_out, nB);
}

// round 2
// speedup vs baseline: 1.0894x; 1.0894x over previous
#include <cuda_runtime.h>

// ---------------------------------------------------------------------------
// M1_17008070492428: batched tiny Hopfield attention + classifier head.
//   B=131072 samples, each (S=14, D=16) -> (7,) softmax probs.
// R2: QKV projection moved to tf32 mma.sync tensor cores (shared weights,
//     bias folded into the MMA C operand); attention stays scalar f32x2.
// ---------------------------------------------------------------------------

typedef unsigned long long u64;
typedef unsigned int u32;

#define LN_EPS 1e-5f
constexpr int ROWW = 20;            // padded row stride (floats)
constexpr int TILE = 16 * ROWW;     // 320 floats per 16x16 tile
constexpr int GW   = 4 * TILE + 16; // per-group smem words (XH,Q,K,V,Tb)

__device__ __forceinline__ u64 ffma2(u64 a, u64 b, u64 c) {
    u64 d; asm("fma.rn.f32x2 %0, %1, %2, %3;" : "=l"(d) : "l"(a), "l"(b), "l"(c)); return d;
}
__device__ __forceinline__ u64 fmul2(u64 a, u64 b) {
    u64 d; asm("mul.rn.f32x2 %0, %1, %2;" : "=l"(d) : "l"(a), "l"(b)); return d;
}
__device__ __forceinline__ u64 pack2(float lo, float hi) {
    u64 r; asm("mov.b64 %0, {%1, %2};" : "=l"(r) : "f"(lo), "f"(hi)); return r;
}
__device__ __forceinline__ float hsum2(u64 v) {
    float lo, hi; asm("mov.b64 {%0, %1}, %2;" : "=f"(lo), "=f"(hi) : "l"(v)); return lo + hi;
}
__device__ __forceinline__ u32 cvt_tf32(float x) {
    u32 r; asm("cvt.rna.tf32.f32 %0, %1;" : "=r"(r) : "f"(x)); return r;
}
__device__ __forceinline__ void mma8(float& d0, float& d1, float& d2, float& d3,
                                     u32 a0, u32 a1, u32 a2, u32 a3,
                                     u32 b0, u32 b1,
                                     float c0, float c1, float c2, float c3) {
    asm("mma.sync.aligned.m16n8k8.row.col.f32.tf32.tf32.f32 "
        "{%0,%1,%2,%3},{%4,%5,%6,%7},{%8,%9},{%10,%11,%12,%13};"
        : "=f"(d0), "=f"(d1), "=f"(d2), "=f"(d3)
        : "r"(a0), "r"(a1), "r"(a2), "r"(a3), "r"(b0), "r"(b1),
          "f"(c0), "f"(c1), "f"(c2), "f"(c3));
}

struct __align__(16) Params {
    float wq[16][16], wk[16][16], wv[16][16];  // LN-gamma folded in
    float bq[16], bk[16], bv[16];              // LN-beta folded in
    float M[7][16];                            // Wb @ Wo
    float ez[8];
    float wm[16];                              // Wm padded with zeros
};
__device__ Params g_P;

__global__ void setup_kernel(
    const float* __restrict__ lnqg, const float* __restrict__ lnqb,
    const float* __restrict__ lnkg, const float* __restrict__ lnkb,
    const float* __restrict__ lnvg, const float* __restrict__ lnvb,
    const float* __restrict__ Wq,  const float* __restrict__ bq,
    const float* __restrict__ Wk,  const float* __restrict__ bk,
    const float* __restrict__ Wv,  const float* __restrict__ bv,
    const float* __restrict__ Wo,  const float* __restrict__ bo,
    const float* __restrict__ Wm,  const float* __restrict__ bm,
    const float* __restrict__ Wb,  const float* __restrict__ bb)
{
    const int t = threadIdx.x;           // 256 threads, 1 block
    const int e = t >> 4, d = t & 15;
    g_P.wq[e][d] = Wq[e * 16 + d] * lnqg[d];
    g_P.wk[e][d] = Wk[e * 16 + d] * lnkg[d];
    g_P.wv[e][d] = Wv[e * 16 + d] * lnvg[d];
    if (t < 16) {
        float aq = bq[t], ak = bk[t], av = bv[t];
        #pragma unroll
        for (int i = 0; i < 16; i++) {
            aq = fmaf(lnqb[i], Wq[t * 16 + i], aq);
            ak = fmaf(lnkb[i], Wk[t * 16 + i], ak);
            av = fmaf(lnvb[i], Wv[t * 16 + i], av);
        }
        g_P.bq[t] = aq; g_P.bk[t] = ak; g_P.bv[t] = av;
        g_P.wm[t] = (t < 14) ? Wm[t] : 0.f;
    }
    if (t < 112) {
        const int c = t >> 4, dd = t & 15;
        float s = 0.f;
        for (int o = 0; o < 128; o++)
            s = fmaf(Wb[c * 128 + o], Wo[o * 16 + dd], s);
        g_P.M[c][dd] = s;
    }
    if (t >= 112 && t < 119) {
        const int c = t - 112;
        float c0 = 0.f;
        for (int s = 0; s < 14; s++) c0 += Wm[s];
        float z = bb[c];
        const float bmv = bm[0];
        for (int o = 0; o < 128; o++)
            z = fmaf(Wb[c * 128 + o], fmaf(c0, bo[o], bmv), z);
        g_P.ez[c] = z;
    }
    if (t == 119) g_P.ez[7] = 0.f;
}

__global__ __launch_bounds__(128, 4) void hopfield_kernel(
    const float* __restrict__ x, float* __restrict__ out, int nB)
{
    __shared__ __align__(16) float sm[8 * GW];
    const int tid  = threadIdx.x;
    const int lane = tid & 31;
    const int t    = lane & 15;                  // lane within sample group
    const int wid  = tid >> 5;
    const int g    = (wid << 1) | (lane >> 4);   // group 0..7 in block

    float* S  = sm + g * GW;
    float* XH = S;                // 16 x ROWW : input / xhat / weighted-O
    float* Qb = S + TILE;
    float* Kb = S + 2 * TILE;
    float* Vb = S + 3 * TILE;
    float* Tb = S + 4 * TILE;     // 16 : t-vector

    float* WA = sm + (wid * 2) * GW;       // warp's sample-A tile base
    float* WB = sm + (wid * 2 + 1) * GW;   // warp's sample-B tile base

    const int fg = lane >> 2;      // mma fragment group (row)
    const int tg = lane & 3;       // mma thread-in-group (col)

    // ---- preload weight B-fragments (tf32) and bias C-fragments ----
    u32   bw[3][2][2][2];          // [proj][ntile][kstep][reg]
    float bs[3][2][2];             // [proj][ntile][col-parity]
    {
        const float* Wp[3] = { &g_P.wq[0][0], &g_P.wk[0][0], &g_P.wv[0][0] };
        const float* Bp[3] = { g_P.bq, g_P.bk, g_P.bv };
        #pragma unroll
        for (int p = 0; p < 3; p++) {
            #pragma unroll
            for (int nt = 0; nt < 2; nt++) {
                #pragma unroll
                for (int ks = 0; ks < 2; ks++) {
                    const float* base = Wp[p] + (fg + 8 * nt) * 16 + 8 * ks;
                    bw[p][nt][ks][0] = cvt_tf32(__ldg(base + tg));
                    bw[p][nt][ks][1] = cvt_tf32(__ldg(base + tg + 4));
                }
                bs[p][nt][0] = __ldg(Bp[p] + 2 * tg + 8 * nt);
                bs[p][nt][1] = __ldg(Bp[p] + 2 * tg + 8 * nt + 1);
            }
        }
    }
    const float wmq = g_P.wm[t];   // 0 for t >= 14

    for (long long base = (long long)blockIdx.x * 8; base < nB;
         base += (long long)gridDim.x * 8)
    {
        const long long samp = base + g;

        // ------- warp-cooperative load of 2 samples (coalesced float4) -------
        {
            const float4* pA = (const float4*)(x + (base + 2 * wid) * 224);
            const float4* pB = (const float4*)(x + (base + 2 * wid + 1) * 224);
            #pragma unroll
            for (int j = 0; j < 4; j++) {
                int i = lane + 32 * j;
                if (i < 112) {
                    bool a = (i < 56);
                    int ii = a ? i : i - 56;
                    float4 v = a ? __ldg(pA + ii) : __ldg(pB + ii);
                    float* dst = a ? WA : WB;
                    *(float4*)&dst[(ii >> 2) * ROWW + ((ii & 3) << 2)] = v;
                }
            }
            if (lane < 16) {   // zero pad rows 14,15 of both xhat tiles
                float* dst = (lane < 8) ? WA : WB;
                int r = 14 + ((lane >> 2) & 1);
                *(float4*)&dst[r * ROWW + ((lane & 3) << 2)] = make_float4(0.f, 0.f, 0.f, 0.f);
            }
        }
        __syncwarp();

        // ------- LayerNorm (row per lane), write xhat in place -------
        if (t < 14) {
            float* row = &XH[t * ROWW];
            float4 a = ((const float4*)row)[0];
            float4 b = ((const float4*)row)[1];
            float4 c = ((const float4*)row)[2];
            float4 d = ((const float4*)row)[3];
            float s1 = ((a.x + a.y) + (a.z + a.w)) + ((b.x + b.y) + (b.z + b.w))
                     + ((c.x + c.y) + (c.z + c.w)) + ((d.x + d.y) + (d.z + d.w));
            float s2 = a.x * a.x;
            s2 = fmaf(a.y, a.y, s2); s2 = fmaf(a.z, a.z, s2); s2 = fmaf(a.w, a.w, s2);
            s2 = fmaf(b.x, b.x, s2); s2 = fmaf(b.y, b.y, s2); s2 = fmaf(b.z, b.z, s2); s2 = fmaf(b.w, b.w, s2);
            s2 = fmaf(c.x, c.x, s2); s2 = fmaf(c.y, c.y, s2); s2 = fmaf(c.z, c.z, s2); s2 = fmaf(c.w, c.w, s2);
            s2 = fmaf(d.x, d.x, s2); s2 = fmaf(d.y, d.y, s2); s2 = fmaf(d.z, d.z, s2); s2 = fmaf(d.w, d.w, s2);
            const float m   = s1 * 0.0625f;
            const float var = fmaf(-m, m, s2 * 0.0625f);
            const float rs  = rsqrtf(var + LN_EPS);
            const float mrs = m * rs;
            a.x = fmaf(a.x, rs, -mrs); a.y = fmaf(a.y, rs, -mrs);
            a.z = fmaf(a.z, rs, -mrs); a.w = fmaf(a.w, rs, -mrs);
            b.x = fmaf(b.x, rs, -mrs); b.y = fmaf(b.y, rs, -mrs);
            b.z = fmaf(b.z, rs, -mrs); b.w = fmaf(b.w, rs, -mrs);
            c.x = fmaf(c.x, rs, -mrs); c.y = fmaf(c.y, rs, -mrs);
            c.z = fmaf(c.z, rs, -mrs); c.w = fmaf(c.w, rs, -mrs);
            d.x = fmaf(d.x, rs, -mrs); d.y = fmaf(d.y, rs, -mrs);
            d.z = fmaf(d.z, rs, -mrs); d.w = fmaf(d.w, rs, -mrs);
            ((float4*)row)[0] = a; ((float4*)row)[1] = b;
            ((float4*)row)[2] = c; ((float4*)row)[3] = d;
        }
        __syncwarp();

        // ------- QKV via tf32 tensor-core mma (whole warp per sample) -------
        #pragma unroll
        for (int smp = 0; smp < 2; smp++) {
            float* XS = smp ? WB : WA;
            u32 a0 = cvt_tf32(XS[fg * ROWW + tg]);
            u32 a1 = cvt_tf32(XS[(fg + 8) * ROWW + tg]);
            u32 a2 = cvt_tf32(XS[fg * ROWW + tg + 4]);
            u32 a3 = cvt_tf32(XS[(fg + 8) * ROWW + tg + 4]);
            u32 a4 = cvt_tf32(XS[fg * ROWW + tg + 8]);
            u32 a5 = cvt_tf32(XS[(fg + 8) * ROWW + tg + 8]);
            u32 a6 = cvt_tf32(XS[fg * ROWW + tg + 12]);
            u32 a7 = cvt_tf32(XS[(fg + 8) * ROWW + tg + 12]);
            #pragma unroll
            for (int p = 0; p < 3; p++) {
                float* P = XS + (p + 1) * TILE;
                #pragma unroll
                for (int nt = 0; nt < 2; nt++) {
                    float d0, d1, d2, d3;
                    mma8(d0, d1, d2, d3, a0, a1, a2, a3,
                         bw[p][nt][0][0], bw[p][nt][0][1],
                         bs[p][nt][0], bs[p][nt][1], bs[p][nt][0], bs[p][nt][1]);
                    mma8(d0, d1, d2, d3, a4, a5, a6, a7,
                         bw[p][nt][1][0], bw[p][nt][1][1], d0, d1, d2, d3);
                    *(float2*)&P[fg * ROWW + 2 * tg + 8 * nt]       = make_float2(d0, d1);
                    *(float2*)&P[(fg + 8) * ROWW + 2 * tg + 8 * nt] = make_float2(d2, d3);
                }
            }
        }
        __syncwarp();

        // ------- attention row q = t : scores, softmax, O row -------
        if (t < 14) {
            u64 qr[8];
            {
                const ulonglong2* q2 = (const ulonglong2*)&Qb[t * ROWW];
                #pragma unroll
                for (int i = 0; i < 4; i++) {
                    ulonglong2 v = q2[i]; qr[2 * i] = v.x; qr[2 * i + 1] = v.y;
                }
            }
            float sc[14];
            float mx = -1e30f;
            #pragma unroll
            for (int k = 0; k < 14; k++) {
                const ulonglong2* kr = (const ulonglong2*)&Kb[k * ROWW];
                u64 a = 0ull;
                #pragma unroll
                for (int i = 0; i < 4; i++) {
                    ulonglong2 kp = kr[i];
                    a = ffma2(qr[2 * i], kp.x, a);
                    a = ffma2(qr[2 * i + 1], kp.y, a);
                }
                sc[k] = hsum2(a);
                mx = fmaxf(mx, sc[k]);
            }
            float ssum = 0.f;
            #pragma unroll
            for (int k = 0; k < 14; k++) { sc[k] = __expf(sc[k] - mx); ssum += sc[k]; }
            const float inv = __fdividef(1.f, ssum);

            u64 o[8] = {0ull, 0ull, 0ull, 0ull, 0ull, 0ull, 0ull, 0ull};
            #pragma unroll
            for (int k = 0; k < 14; k++) {
                const u64 a2 = pack2(sc[k], sc[k]);
                const ulonglong2* vr = (const ulonglong2*)&Vb[k * ROWW];
                #pragma unroll
                for (int i = 0; i < 4; i++) {
                    ulonglong2 vp = vr[i];
                    o[2 * i]     = ffma2(a2, vp.x, o[2 * i]);
                    o[2 * i + 1] = ffma2(a2, vp.y, o[2 * i + 1]);
                }
            }
            const float w  = wmq * inv;
            const u64  w2  = pack2(w, w);
            ulonglong2* orow = (ulonglong2*)&XH[t * ROWW];
            #pragma unroll
            for (int i = 0; i < 4; i++) {
                ulonglong2 st;
                st.x = fmul2(o[2 * i], w2);
                st.y = fmul2(o[2 * i + 1], w2);
                orow[i] = st;
            }
        }
        __syncwarp();

        // ------- t[d] = sum_s weightedO[s,d] -------
        float td = 0.f;
        #pragma unroll
        for (int s = 0; s < 14; s++) td += XH[s * ROWW + t];
        Tb[t] = td;
        __syncwarp();

        // ------- z = M @ t + ez ; softmax over 7 across lanes 0..6 -------
        float z = -1e30f;
        if (t < 7) {
            const ulonglong2* tv = (const ulonglong2*)Tb;
            const ulonglong2* pm = (const ulonglong2*)g_P.M[t];
            u64 a = 0ull;
            #pragma unroll
            for (int i = 0; i < 4; i++) {
                ulonglong2 tp = tv[i];
                ulonglong2 mp = pm[i];
                a = ffma2(mp.x, tp.x, a);
                a = ffma2(mp.y, tp.y, a);
            }
            z = hsum2(a) + g_P.ez[t];
        }
        float m2 = z;
        m2 = fmaxf(m2, __shfl_xor_sync(0xffffffffu, m2, 4, 8));
        m2 = fmaxf(m2, __shfl_xor_sync(0xffffffffu, m2, 2, 8));
        m2 = fmaxf(m2, __shfl_xor_sync(0xffffffffu, m2, 1, 8));
        float exz = __expf(z - m2);
        float sz = exz;
        sz += __shfl_xor_sync(0xffffffffu, sz, 4, 8);
        sz += __shfl_xor_sync(0xffffffffu, sz, 2, 8);
        sz += __shfl_xor_sync(0xffffffffu, sz, 1, 8);
        if (t < 7) out[samp * 7 + t] = __fdividef(exz, sz);
        __syncwarp();
    }
}

extern "C" void kernel_launch(void* const* d_in, const int* in_sizes, int n_in,
                              void* d_out, int out_size)
{
    const float* sample = (const float*)d_in[0];
    setup_kernel<<<1, 256>>>(
        (const float*)d_in[1],  (const float*)d_in[2],
        (const float*)d_in[3],  (const float*)d_in[4],
        (const float*)d_in[5],  (const float*)d_in[6],
        (const float*)d_in[7],  (const float*)d_in[8],
        (const float*)d_in[9],  (const float*)d_in[10],
        (const float*)d_in[11], (const float*)d_in[12],
        (const float*)d_in[13], (const float*)d_in[14],
        (const float*)d_in[15], (const float*)d_in[16],
        (const float*)d_in[17], (const float*)d_in[18]);

    const int nB = in_sizes[0] / 224;   // B = 131072
    hopfield_kernel<<<2048, 128>>>(sample, (float*)d_out, nB);
}

// round 4
// speedup vs baseline: 1.4056x; 1.2902x over previous
#include <cuda_runtime.h>

// ---------------------------------------------------------------------------
// M1_17008070492428: batched tiny Hopfield attention + classifier head.
//   B=131072 samples, each (S=14, D=16) -> (7,) softmax probs.
// R4 = R3 with two tail-phase bug fixes:
//   (1) out = ex/se   (the 4x compensation was wrong: the {4,8,16} xor
//       reduction sums each class exactly once at fixed tg)
//   (2) ez added once AFTER the quad reduction (was added by all 4 lanes)
// Pipeline: PI-permuted QKV weights make each MMA C-fragment coincide with
// the next MMA's A/B fragment layout; Q,K,P stay in registers; V goes
// through a 16x24 smem transpose tile; everything else is shuffles.
// ---------------------------------------------------------------------------

typedef unsigned int u32;
#define LN_EPS 1e-5f
#define FULLM 0xffffffffu

__device__ __forceinline__ u32 cvt_tf32(float x) {
    u32 r; asm("cvt.rna.tf32.f32 %0, %1;" : "=r"(r) : "f"(x)); return r;
}
__device__ __forceinline__ void mma8(float& d0, float& d1, float& d2, float& d3,
                                     u32 a0, u32 a1, u32 a2, u32 a3,
                                     u32 b0, u32 b1,
                                     float c0, float c1, float c2, float c3) {
    asm("mma.sync.aligned.m16n8k8.row.col.f32.tf32.tf32.f32 "
        "{%0,%1,%2,%3},{%4,%5,%6,%7},{%8,%9},{%10,%11,%12,%13};"
        : "=f"(d0), "=f"(d1), "=f"(d2), "=f"(d3)
        : "r"(a0), "r"(a1), "r"(a2), "r"(a3), "r"(b0), "r"(b1),
          "f"(c0), "f"(c1), "f"(c2), "f"(c3));
}

struct __align__(16) Params {
    float wq[16][16], wk[16][16], wv[16][16];  // PI-permuted rows, LN-gamma folded
    float bq[16], bk[16], bv[16];              // PI-permuted, LN-beta folded
    float M[7][16];                            // Wb @ Wo (true-d columns)
    float ez[8];
    float wm[16];                              // Wm padded with zeros
};
__device__ Params g_P;

__global__ void setup_kernel(
    const float* __restrict__ lnqg, const float* __restrict__ lnqb,
    const float* __restrict__ lnkg, const float* __restrict__ lnkb,
    const float* __restrict__ lnvg, const float* __restrict__ lnvb,
    const float* __restrict__ Wq,  const float* __restrict__ bq,
    const float* __restrict__ Wk,  const float* __restrict__ bk,
    const float* __restrict__ Wv,  const float* __restrict__ bv,
    const float* __restrict__ Wo,  const float* __restrict__ bo,
    const float* __restrict__ Wm,  const float* __restrict__ bm,
    const float* __restrict__ Wb,  const float* __restrict__ bb)
{
    const int PI[16] = {0,4,1,5,2,6,3,7, 8,12,9,13,10,14,11,15};
    const int t = threadIdx.x;           // 256 threads, 1 block
    const int e = t >> 4, d = t & 15;
    const int pe = PI[e];
    g_P.wq[e][d] = Wq[pe * 16 + d] * lnqg[d];
    g_P.wk[e][d] = Wk[pe * 16 + d] * lnkg[d];
    g_P.wv[e][d] = Wv[pe * 16 + d] * lnvg[d];
    if (t < 16) {
        const int p = PI[t];
        float aq = bq[p], ak = bk[p], av = bv[p];
        #pragma unroll
        for (int i = 0; i < 16; i++) {
            aq = fmaf(lnqb[i], Wq[p * 16 + i], aq);
            ak = fmaf(lnkb[i], Wk[p * 16 + i], ak);
            av = fmaf(lnvb[i], Wv[p * 16 + i], av);
        }
        g_P.bq[t] = aq; g_P.bk[t] = ak; g_P.bv[t] = av;
        g_P.wm[t] = (t < 14) ? Wm[t] : 0.f;
    }
    if (t < 112) {
        const int c = t >> 4, dd = t & 15;
        float s = 0.f;
        for (int o = 0; o < 128; o++)
            s = fmaf(Wb[c * 128 + o], Wo[o * 16 + dd], s);
        g_P.M[c][dd] = s;
    }
    if (t >= 112 && t < 119) {
        const int c = t - 112;
        float c0 = 0.f;
        for (int s = 0; s < 14; s++) c0 += Wm[s];
        float z = bb[c];
        const float bmv = bm[0];
        for (int o = 0; o < 128; o++)
            z = fmaf(Wb[c * 128 + o], fmaf(c0, bo[o], bmv), z);
        g_P.ez[c] = z;
    }
    if (t == 119) g_P.ez[7] = 0.f;
}

__global__ __launch_bounds__(128, 4) void hopfield_kernel(
    const float* __restrict__ x, float* __restrict__ out, int nB)
{
    __shared__ __align__(16) float smVt[4][2][16 * 24];   // 12 KB
    const int tid  = threadIdx.x;
    const int lane = tid & 31;
    const int wid  = tid >> 5;
    const int fg   = lane >> 2;     // 0..7  (row group / B n-col)
    const int tg   = lane & 3;      // 0..3  (thread-in-quad)

    // ---- persistent weight B-fragments (tf32) + bias C-fragments ----
    u32   bw[3][2][2][2];           // [proj][ntile][kstep][reg]
    float bs[3][2][2];
    {
        const float* Wp[3] = { &g_P.wq[0][0], &g_P.wk[0][0], &g_P.wv[0][0] };
        const float* Bp[3] = { g_P.bq, g_P.bk, g_P.bv };
        #pragma unroll
        for (int p = 0; p < 3; p++) {
            #pragma unroll
            for (int nt = 0; nt < 2; nt++) {
                #pragma unroll
                for (int ks = 0; ks < 2; ks++) {
                    const float* base = Wp[p] + (fg + 8 * nt) * 16 + 8 * ks;
                    bw[p][nt][ks][0] = cvt_tf32(__ldg(base + tg));
                    bw[p][nt][ks][1] = cvt_tf32(__ldg(base + tg + 4));
                }
                bs[p][nt][0] = __ldg(Bp[p] + 2 * tg + 8 * nt);
                bs[p][nt][1] = __ldg(Bp[p] + 2 * tg + 8 * nt + 1);
            }
        }
    }
    const float wmLo = g_P.wm[fg];
    const float wmHi = g_P.wm[fg + 8];      // 0 for rows 14,15
    float4 mz = make_float4(0.f, 0.f, 0.f, 0.f);
    float ezv = 0.f;
    if (fg < 7) {
        float2 a = *(const float2*)&g_P.M[fg][2 * tg];
        float2 b = *(const float2*)&g_P.M[fg][8 + 2 * tg];
        mz = make_float4(a.x, a.y, b.x, b.y);
        ezv = g_P.ez[fg];
    }

    const int totalWarps = gridDim.x * 4;
    for (int s0 = (blockIdx.x * 4 + wid) * 2; s0 < nB; s0 += totalWarps * 2) {
        #pragma unroll
        for (int smp = 0; smp < 2; smp++) {
            const int samp = s0 + smp;
            if (samp >= nB) break;
            float* Vt = smVt[wid][smp];
            const float* xs = x + (long long)samp * 224;

            // ---- load x directly in fragment layout + LN via quad shuffles ----
            float xlo[4], xhi[4];
            #pragma unroll
            for (int u = 0; u < 4; u++) {
                xlo[u] = __ldg(xs + fg * 16 + tg + 4 * u);
                xhi[u] = (fg < 6) ? __ldg(xs + (fg + 8) * 16 + tg + 4 * u) : 0.f;
            }
            float s1l = ((xlo[0] + xlo[1]) + (xlo[2] + xlo[3]));
            float s2l = xlo[0] * xlo[0];
            s2l = fmaf(xlo[1], xlo[1], s2l); s2l = fmaf(xlo[2], xlo[2], s2l); s2l = fmaf(xlo[3], xlo[3], s2l);
            float s1h = ((xhi[0] + xhi[1]) + (xhi[2] + xhi[3]));
            float s2h = xhi[0] * xhi[0];
            s2h = fmaf(xhi[1], xhi[1], s2h); s2h = fmaf(xhi[2], xhi[2], s2h); s2h = fmaf(xhi[3], xhi[3], s2h);
            s1l += __shfl_xor_sync(FULLM, s1l, 1); s1l += __shfl_xor_sync(FULLM, s1l, 2);
            s2l += __shfl_xor_sync(FULLM, s2l, 1); s2l += __shfl_xor_sync(FULLM, s2l, 2);
            s1h += __shfl_xor_sync(FULLM, s1h, 1); s1h += __shfl_xor_sync(FULLM, s1h, 2);
            s2h += __shfl_xor_sync(FULLM, s2h, 1); s2h += __shfl_xor_sync(FULLM, s2h, 2);
            const float mL = s1l * 0.0625f;
            const float rL = rsqrtf(fmaf(-mL, mL, s2l * 0.0625f) + LN_EPS);
            const float mH = s1h * 0.0625f;
            const float rH = rsqrtf(fmaf(-mH, mH, s2h * 0.0625f) + LN_EPS);
            u32 a0 = cvt_tf32((xlo[0] - mL) * rL), a1 = cvt_tf32((xhi[0] - mH) * rH);
            u32 a2 = cvt_tf32((xlo[1] - mL) * rL), a3 = cvt_tf32((xhi[1] - mH) * rH);
            u32 a4 = cvt_tf32((xlo[2] - mL) * rL), a5 = cvt_tf32((xhi[2] - mH) * rH);
            u32 a6 = cvt_tf32((xlo[3] - mL) * rL), a7 = cvt_tf32((xhi[3] - mH) * rH);

            // ---- QKV (PI-permuted): C-frags land in true-d layout ----
            float Q[8], K[8], V[8];
            #pragma unroll
            for (int p = 0; p < 3; p++) {
                float* D = (p == 0) ? Q : ((p == 1) ? K : V);
                #pragma unroll
                for (int nt = 0; nt < 2; nt++) {
                    float d0, d1, d2, d3;
                    mma8(d0, d1, d2, d3, a0, a1, a2, a3,
                         bw[p][nt][0][0], bw[p][nt][0][1],
                         bs[p][nt][0], bs[p][nt][1], bs[p][nt][0], bs[p][nt][1]);
                    mma8(d0, d1, d2, d3, a4, a5, a6, a7,
                         bw[p][nt][1][0], bw[p][nt][1][1], d0, d1, d2, d3);
                    D[nt * 4 + 0] = d0; D[nt * 4 + 1] = d1;
                    D[nt * 4 + 2] = d2; D[nt * 4 + 3] = d3;
                }
            }

            // ---- stage V transposed: Vt[d][key], stride 24 (conflict-free) ----
            Vt[ tg       * 24 + fg    ] = V[0];
            Vt[(tg + 4)  * 24 + fg    ] = V[1];
            Vt[ tg       * 24 + fg + 8] = V[2];
            Vt[(tg + 4)  * 24 + fg + 8] = V[3];
            Vt[(tg + 8)  * 24 + fg    ] = V[4];
            Vt[(tg + 12) * 24 + fg    ] = V[5];
            Vt[(tg + 8)  * 24 + fg + 8] = V[6];
            Vt[(tg + 12) * 24 + fg + 8] = V[7];

            // ---- S = Q K^T : pure register MMA ----
            u32 qa0 = cvt_tf32(Q[0]), qa1 = cvt_tf32(Q[2]), qa2 = cvt_tf32(Q[1]), qa3 = cvt_tf32(Q[3]);
            u32 qa4 = cvt_tf32(Q[4]), qa5 = cvt_tf32(Q[6]), qa6 = cvt_tf32(Q[5]), qa7 = cvt_tf32(Q[7]);
            float t0, t1, t2, t3, u0, u1, u2, u3;
            mma8(t0, t1, t2, t3, qa0, qa1, qa2, qa3, cvt_tf32(K[0]), cvt_tf32(K[1]), 0.f, 0.f, 0.f, 0.f);
            mma8(t0, t1, t2, t3, qa4, qa5, qa6, qa7, cvt_tf32(K[4]), cvt_tf32(K[5]), t0, t1, t2, t3);
            mma8(u0, u1, u2, u3, qa0, qa1, qa2, qa3, cvt_tf32(K[2]), cvt_tf32(K[3]), 0.f, 0.f, 0.f, 0.f);
            mma8(u0, u1, u2, u3, qa4, qa5, qa6, qa7, cvt_tf32(K[6]), cvt_tf32(K[7]), u0, u1, u2, u3);
            if (tg == 3) { u0 = -1e30f; u1 = -1e30f; u2 = -1e30f; u3 = -1e30f; }  // keys 14,15

            // ---- softmax rows (quad shuffles), fold wm*inv into P ----
            float mLo = fmaxf(fmaxf(t0, t1), fmaxf(u0, u1));
            mLo = fmaxf(mLo, __shfl_xor_sync(FULLM, mLo, 1));
            mLo = fmaxf(mLo, __shfl_xor_sync(FULLM, mLo, 2));
            float mHi = fmaxf(fmaxf(t2, t3), fmaxf(u2, u3));
            mHi = fmaxf(mHi, __shfl_xor_sync(FULLM, mHi, 1));
            mHi = fmaxf(mHi, __shfl_xor_sync(FULLM, mHi, 2));
            float e0 = __expf(t0 - mLo), e1 = __expf(t1 - mLo), e4 = __expf(u0 - mLo), e5 = __expf(u1 - mLo);
            float e2 = __expf(t2 - mHi), e3 = __expf(t3 - mHi), e6 = __expf(u2 - mHi), e7 = __expf(u3 - mHi);
            float sl = (e0 + e1) + (e4 + e5);
            sl += __shfl_xor_sync(FULLM, sl, 1); sl += __shfl_xor_sync(FULLM, sl, 2);
            float sh = (e2 + e3) + (e6 + e7);
            sh += __shfl_xor_sync(FULLM, sh, 1); sh += __shfl_xor_sync(FULLM, sh, 2);
            const float wl = wmLo * __fdividef(1.f, sl);
            const float wh = wmHi * __fdividef(1.f, sh);
            u32 pa0 = cvt_tf32(e0 * wl), pa1 = cvt_tf32(e2 * wh), pa2 = cvt_tf32(e1 * wl), pa3 = cvt_tf32(e3 * wh);
            u32 pb0 = cvt_tf32(e4 * wl), pb1 = cvt_tf32(e6 * wh), pb2 = cvt_tf32(e5 * wl), pb3 = cvt_tf32(e7 * wh);

            __syncwarp();
            const float2 v00 = *(const float2*)&Vt[fg * 24 + 2 * tg];
            const float2 v01 = *(const float2*)&Vt[fg * 24 + 8 + 2 * tg];
            const float2 v10 = *(const float2*)&Vt[(fg + 8) * 24 + 2 * tg];
            const float2 v11 = *(const float2*)&Vt[(fg + 8) * 24 + 8 + 2 * tg];

            // ---- O = P' V (key dim permuted consistently on both sides) ----
            float o0, o1, o2, o3, p0, p1, p2, p3;
            mma8(o0, o1, o2, o3, pa0, pa1, pa2, pa3, cvt_tf32(v00.x), cvt_tf32(v00.y), 0.f, 0.f, 0.f, 0.f);
            mma8(o0, o1, o2, o3, pb0, pb1, pb2, pb3, cvt_tf32(v01.x), cvt_tf32(v01.y), o0, o1, o2, o3);
            mma8(p0, p1, p2, p3, pa0, pa1, pa2, pa3, cvt_tf32(v10.x), cvt_tf32(v10.y), 0.f, 0.f, 0.f, 0.f);
            mma8(p0, p1, p2, p3, pb0, pb1, pb2, pb3, cvt_tf32(v11.x), cvt_tf32(v11.y), p0, p1, p2, p3);

            // ---- t[d]: column sums over q (rows already weighted) ----
            float c0 = o0 + o2, c1 = o1 + o3, c2 = p0 + p2, c3 = p1 + p3;
            #pragma unroll
            for (int off = 4; off <= 16; off <<= 1) {
                c0 += __shfl_xor_sync(FULLM, c0, off);
                c1 += __shfl_xor_sync(FULLM, c1, off);
                c2 += __shfl_xor_sync(FULLM, c2, off);
                c3 += __shfl_xor_sync(FULLM, c3, off);
            }

            // ---- z[c] per fg-group (partial dot; ez added ONCE after quad sum) ----
            float z = (fg < 7)
                ? fmaf(mz.x, c0, fmaf(mz.y, c1, fmaf(mz.z, c2, mz.w * c3)))
                : 0.f;
            z += __shfl_xor_sync(FULLM, z, 1);
            z += __shfl_xor_sync(FULLM, z, 2);
            float zq = (fg < 7) ? (z + ezv) : -1e30f;
            float zm = zq;
            zm = fmaxf(zm, __shfl_xor_sync(FULLM, zm, 4));
            zm = fmaxf(zm, __shfl_xor_sync(FULLM, zm, 8));
            zm = fmaxf(zm, __shfl_xor_sync(FULLM, zm, 16));
            float ex = __expf(zq - zm);
            float se = ex;
            se += __shfl_xor_sync(FULLM, se, 4);
            se += __shfl_xor_sync(FULLM, se, 8);
            se += __shfl_xor_sync(FULLM, se, 16);
            if (tg == 0 && fg < 7)
                out[samp * 7 + fg] = __fdividef(ex, se);
        }
    }
}

extern "C" void kernel_launch(void* const* d_in, const int* in_sizes, int n_in,
                              void* d_out, int out_size)
{
    const float* sample = (const float*)d_in[0];
    setup_kernel<<<1, 256>>>(
        (const float*)d_in[1],  (const float*)d_in[2],
        (const float*)d_in[3],  (const float*)d_in[4],
        (const float*)d_in[5],  (const float*)d_in[6],
        (const float*)d_in[7],  (const float*)d_in[8],
        (const float*)d_in[9],  (const float*)d_in[10],
        (const float*)d_in[11], (const float*)d_in[12],
        (const float*)d_in[13], (const float*)d_in[14],
        (const float*)d_in[15], (const float*)d_in[16],
        (const float*)d_in[17], (const float*)d_in[18]);

    const int nB = in_sizes[0] / 224;   // B = 131072
    hopfield_kernel<<<2048, 128>>>(sample, (float*)d_out, nB);
}

// round 5
// speedup vs baseline: 1.4070x; 1.0011x over previous
#include <cuda_runtime.h>

// ---------------------------------------------------------------------------
// M1_17008070492428: batched tiny Hopfield attention + classifier head.
//   B=131072 samples, each (S=14, D=16) -> (7,) softmax probs.
// R4 = R3 with two tail-phase bug fixes:
//   (1) out = ex/se   (the 4x compensation was wrong: the {4,8,16} xor
//       reduction sums each class exactly once at fixed tg)
//   (2) ez added once AFTER the quad reduction (was added by all 4 lanes)
// Pipeline: PI-permuted QKV weights make each MMA C-fragment coincide with
// the next MMA's A/B fragment layout; Q,K,P stay in registers; V goes
// through a 16x24 smem transpose tile; everything else is shuffles.
// ---------------------------------------------------------------------------

typedef unsigned int u32;
#define LN_EPS 1e-5f
#define FULLM 0xffffffffu

__device__ __forceinline__ u32 cvt_tf32(float x) {
    u32 r; asm("cvt.rna.tf32.f32 %0, %1;" : "=r"(r) : "f"(x)); return r;
}
__device__ __forceinline__ void mma8(float& d0, float& d1, float& d2, float& d3,
                                     u32 a0, u32 a1, u32 a2, u32 a3,
                                     u32 b0, u32 b1,
                                     float c0, float c1, float c2, float c3) {
    asm("mma.sync.aligned.m16n8k8.row.col.f32.tf32.tf32.f32 "
        "{%0,%1,%2,%3},{%4,%5,%6,%7},{%8,%9},{%10,%11,%12,%13};"
        : "=f"(d0), "=f"(d1), "=f"(d2), "=f"(d3)
        : "r"(a0), "r"(a1), "r"(a2), "r"(a3), "r"(b0), "r"(b1),
          "f"(c0), "f"(c1), "f"(c2), "f"(c3));
}

struct __align__(16) Params {
    float wq[16][16], wk[16][16], wv[16][16];  // PI-permuted rows, LN-gamma folded
    float bq[16], bk[16], bv[16];              // PI-permuted, LN-beta folded
    float M[7][16];                            // Wb @ Wo (true-d columns)
    float ez[8];
    float wm[16];                              // Wm padded with zeros
};
__device__ Params g_P;

__global__ void setup_kernel(
    const float* __restrict__ lnqg, const float* __restrict__ lnqb,
    const float* __restrict__ lnkg, const float* __restrict__ lnkb,
    const float* __restrict__ lnvg, const float* __restrict__ lnvb,
    const float* __restrict__ Wq,  const float* __restrict__ bq,
    const float* __restrict__ Wk,  const float* __restrict__ bk,
    const float* __restrict__ Wv,  const float* __restrict__ bv,
    const float* __restrict__ Wo,  const float* __restrict__ bo,
    const float* __restrict__ Wm,  const float* __restrict__ bm,
    const float* __restrict__ Wb,  const float* __restrict__ bb)
{
    const int PI[16] = {0,4,1,5,2,6,3,7, 8,12,9,13,10,14,11,15};
    const int t = threadIdx.x;           // 256 threads, 1 block
    const int e = t >> 4, d = t & 15;
    const int pe = PI[e];
    g_P.wq[e][d] = Wq[pe * 16 + d] * lnqg[d];
    g_P.wk[e][d] = Wk[pe * 16 + d] * lnkg[d];
    g_P.wv[e][d] = Wv[pe * 16 + d] * lnvg[d];
    if (t < 16) {
        const int p = PI[t];
        float aq = bq[p], ak = bk[p], av = bv[p];
        #pragma unroll
        for (int i = 0; i < 16; i++) {
            aq = fmaf(lnqb[i], Wq[p * 16 + i], aq);
            ak = fmaf(lnkb[i], Wk[p * 16 + i], ak);
            av = fmaf(lnvb[i], Wv[p * 16 + i], av);
        }
        g_P.bq[t] = aq; g_P.bk[t] = ak; g_P.bv[t] = av;
        g_P.wm[t] = (t < 14) ? Wm[t] : 0.f;
    }
    if (t < 112) {
        const int c = t >> 4, dd = t & 15;
        float s = 0.f;
        for (int o = 0; o < 128; o++)
            s = fmaf(Wb[c * 128 + o], Wo[o * 16 + dd], s);
        g_P.M[c][dd] = s;
    }
    if (t >= 112 && t < 119) {
        const int c = t - 112;
        float c0 = 0.f;
        for (int s = 0; s < 14; s++) c0 += Wm[s];
        float z = bb[c];
        const float bmv = bm[0];
        for (int o = 0; o < 128; o++)
            z = fmaf(Wb[c * 128 + o], fmaf(c0, bo[o], bmv), z);
        g_P.ez[c] = z;
    }
    if (t == 119) g_P.ez[7] = 0.f;
}

__global__ __launch_bounds__(128, 4) void hopfield_kernel(
    const float* __restrict__ x, float* __restrict__ out, int nB)
{
    __shared__ __align__(16) float smVt[4][2][16 * 24];   // 12 KB
    const int tid  = threadIdx.x;
    const int lane = tid & 31;
    const int wid  = tid >> 5;
    const int fg   = lane >> 2;     // 0..7  (row group / B n-col)
    const int tg   = lane & 3;      // 0..3  (thread-in-quad)

    // ---- persistent weight B-fragments (tf32) + bias C-fragments ----
    u32   bw[3][2][2][2];           // [proj][ntile][kstep][reg]
    float bs[3][2][2];
    {
        const float* Wp[3] = { &g_P.wq[0][0], &g_P.wk[0][0], &g_P.wv[0][0] };
        const float* Bp[3] = { g_P.bq, g_P.bk, g_P.bv };
        #pragma unroll
        for (int p = 0; p < 3; p++) {
            #pragma unroll
            for (int nt = 0; nt < 2; nt++) {
                #pragma unroll
                for (int ks = 0; ks < 2; ks++) {
                    const float* base = Wp[p] + (fg + 8 * nt) * 16 + 8 * ks;
                    bw[p][nt][ks][0] = cvt_tf32(__ldg(base + tg));
                    bw[p][nt][ks][1] = cvt_tf32(__ldg(base + tg + 4));
                }
                bs[p][nt][0] = __ldg(Bp[p] + 2 * tg + 8 * nt);
                bs[p][nt][1] = __ldg(Bp[p] + 2 * tg + 8 * nt + 1);
            }
        }
    }
    const float wmLo = g_P.wm[fg];
    const float wmHi = g_P.wm[fg + 8];      // 0 for rows 14,15
    float4 mz = make_float4(0.f, 0.f, 0.f, 0.f);
    float ezv = 0.f;
    if (fg < 7) {
        float2 a = *(const float2*)&g_P.M[fg][2 * tg];
        float2 b = *(const float2*)&g_P.M[fg][8 + 2 * tg];
        mz = make_float4(a.x, a.y, b.x, b.y);
        ezv = g_P.ez[fg];
    }

    const int totalWarps = gridDim.x * 4;
    for (int s0 = (blockIdx.x * 4 + wid) * 2; s0 < nB; s0 += totalWarps * 2) {
        #pragma unroll
        for (int smp = 0; smp < 2; smp++) {
            const int samp = s0 + smp;
            if (samp >= nB) break;
            float* Vt = smVt[wid][smp];
            const float* xs = x + (long long)samp * 224;

            // ---- load x directly in fragment layout + LN via quad shuffles ----
            float xlo[4], xhi[4];
            #pragma unroll
            for (int u = 0; u < 4; u++) {
                xlo[u] = __ldg(xs + fg * 16 + tg + 4 * u);
                xhi[u] = (fg < 6) ? __ldg(xs + (fg + 8) * 16 + tg + 4 * u) : 0.f;
            }
            float s1l = ((xlo[0] + xlo[1]) + (xlo[2] + xlo[3]));
            float s2l = xlo[0] * xlo[0];
            s2l = fmaf(xlo[1], xlo[1], s2l); s2l = fmaf(xlo[2], xlo[2], s2l); s2l = fmaf(xlo[3], xlo[3], s2l);
            float s1h = ((xhi[0] + xhi[1]) + (xhi[2] + xhi[3]));
            float s2h = xhi[0] * xhi[0];
            s2h = fmaf(xhi[1], xhi[1], s2h); s2h = fmaf(xhi[2], xhi[2], s2h); s2h = fmaf(xhi[3], xhi[3], s2h);
            s1l += __shfl_xor_sync(FULLM, s1l, 1); s1l += __shfl_xor_sync(FULLM, s1l, 2);
            s2l += __shfl_xor_sync(FULLM, s2l, 1); s2l += __shfl_xor_sync(FULLM, s2l, 2);
            s1h += __shfl_xor_sync(FULLM, s1h, 1); s1h += __shfl_xor_sync(FULLM, s1h, 2);
            s2h += __shfl_xor_sync(FULLM, s2h, 1); s2h += __shfl_xor_sync(FULLM, s2h, 2);
            const float mL = s1l * 0.0625f;
            const float rL = rsqrtf(fmaf(-mL, mL, s2l * 0.0625f) + LN_EPS);
            const float mH = s1h * 0.0625f;
            const float rH = rsqrtf(fmaf(-mH, mH, s2h * 0.0625f) + LN_EPS);
            u32 a0 = cvt_tf32((xlo[0] - mL) * rL), a1 = cvt_tf32((xhi[0] - mH) * rH);
            u32 a2 = cvt_tf32((xlo[1] - mL) * rL), a3 = cvt_tf32((xhi[1] - mH) * rH);
            u32 a4 = cvt_tf32((xlo[2] - mL) * rL), a5 = cvt_tf32((xhi[2] - mH) * rH);
            u32 a6 = cvt_tf32((xlo[3] - mL) * rL), a7 = cvt_tf32((xhi[3] - mH) * rH);

            // ---- QKV (PI-permuted): C-frags land in true-d layout ----
            float Q[8], K[8], V[8];
            #pragma unroll
            for (int p = 0; p < 3; p++) {
                float* D = (p == 0) ? Q : ((p == 1) ? K : V);
                #pragma unroll
                for (int nt = 0; nt < 2; nt++) {
                    float d0, d1, d2, d3;
                    mma8(d0, d1, d2, d3, a0, a1, a2, a3,
                         bw[p][nt][0][0], bw[p][nt][0][1],
                         bs[p][nt][0], bs[p][nt][1], bs[p][nt][0], bs[p][nt][1]);
                    mma8(d0, d1, d2, d3, a4, a5, a6, a7,
                         bw[p][nt][1][0], bw[p][nt][1][1], d0, d1, d2, d3);
                    D[nt * 4 + 0] = d0; D[nt * 4 + 1] = d1;
                    D[nt * 4 + 2] = d2; D[nt * 4 + 3] = d3;
                }
            }

            // ---- stage V transposed: Vt[d][key], stride 24 (conflict-free) ----
            Vt[ tg       * 24 + fg    ] = V[0];
            Vt[(tg + 4)  * 24 + fg    ] = V[1];
            Vt[ tg       * 24 + fg + 8] = V[2];
            Vt[(tg + 4)  * 24 + fg + 8] = V[3];
            Vt[(tg + 8)  * 24 + fg    ] = V[4];
            Vt[(tg + 12) * 24 + fg    ] = V[5];
            Vt[(tg + 8)  * 24 + fg + 8] = V[6];
            Vt[(tg + 12) * 24 + fg + 8] = V[7];

            // ---- S = Q K^T : pure register MMA ----
            u32 qa0 = cvt_tf32(Q[0]), qa1 = cvt_tf32(Q[2]), qa2 = cvt_tf32(Q[1]), qa3 = cvt_tf32(Q[3]);
            u32 qa4 = cvt_tf32(Q[4]), qa5 = cvt_tf32(Q[6]), qa6 = cvt_tf32(Q[5]), qa7 = cvt_tf32(Q[7]);
            float t0, t1, t2, t3, u0, u1, u2, u3;
            mma8(t0, t1, t2, t3, qa0, qa1, qa2, qa3, cvt_tf32(K[0]), cvt_tf32(K[1]), 0.f, 0.f, 0.f, 0.f);
            mma8(t0, t1, t2, t3, qa4, qa5, qa6, qa7, cvt_tf32(K[4]), cvt_tf32(K[5]), t0, t1, t2, t3);
            mma8(u0, u1, u2, u3, qa0, qa1, qa2, qa3, cvt_tf32(K[2]), cvt_tf32(K[3]), 0.f, 0.f, 0.f, 0.f);
            mma8(u0, u1, u2, u3, qa4, qa5, qa6, qa7, cvt_tf32(K[6]), cvt_tf32(K[7]), u0, u1, u2, u3);
            if (tg == 3) { u0 = -1e30f; u1 = -1e30f; u2 = -1e30f; u3 = -1e30f; }  // keys 14,15

            // ---- softmax rows (quad shuffles), fold wm*inv into P ----
            float mLo = fmaxf(fmaxf(t0, t1), fmaxf(u0, u1));
            mLo = fmaxf(mLo, __shfl_xor_sync(FULLM, mLo, 1));
            mLo = fmaxf(mLo, __shfl_xor_sync(FULLM, mLo, 2));
            float mHi = fmaxf(fmaxf(t2, t3), fmaxf(u2, u3));
            mHi = fmaxf(mHi, __shfl_xor_sync(FULLM, mHi, 1));
            mHi = fmaxf(mHi, __shfl_xor_sync(FULLM, mHi, 2));
            float e0 = __expf(t0 - mLo), e1 = __expf(t1 - mLo), e4 = __expf(u0 - mLo), e5 = __expf(u1 - mLo);
            float e2 = __expf(t2 - mHi), e3 = __expf(t3 - mHi), e6 = __expf(u2 - mHi), e7 = __expf(u3 - mHi);
            float sl = (e0 + e1) + (e4 + e5);
            sl += __shfl_xor_sync(FULLM, sl, 1); sl += __shfl_xor_sync(FULLM, sl, 2);
            float sh = (e2 + e3) + (e6 + e7);
            sh += __shfl_xor_sync(FULLM, sh, 1); sh += __shfl_xor_sync(FULLM, sh, 2);
            const float wl = wmLo * __fdividef(1.f, sl);
            const float wh = wmHi * __fdividef(1.f, sh);
            u32 pa0 = cvt_tf32(e0 * wl), pa1 = cvt_tf32(e2 * wh), pa2 = cvt_tf32(e1 * wl), pa3 = cvt_tf32(e3 * wh);
            u32 pb0 = cvt_tf32(e4 * wl), pb1 = cvt_tf32(e6 * wh), pb2 = cvt_tf32(e5 * wl), pb3 = cvt_tf32(e7 * wh);

            __syncwarp();
            const float2 v00 = *(const float2*)&Vt[fg * 24 + 2 * tg];
            const float2 v01 = *(const float2*)&Vt[fg * 24 + 8 + 2 * tg];
            const float2 v10 = *(const float2*)&Vt[(fg + 8) * 24 + 2 * tg];
            const float2 v11 = *(const float2*)&Vt[(fg + 8) * 24 + 8 + 2 * tg];

            // ---- O = P' V (key dim permuted consistently on both sides) ----
            float o0, o1, o2, o3, p0, p1, p2, p3;
            mma8(o0, o1, o2, o3, pa0, pa1, pa2, pa3, cvt_tf32(v00.x), cvt_tf32(v00.y), 0.f, 0.f, 0.f, 0.f);
            mma8(o0, o1, o2, o3, pb0, pb1, pb2, pb3, cvt_tf32(v01.x), cvt_tf32(v01.y), o0, o1, o2, o3);
            mma8(p0, p1, p2, p3, pa0, pa1, pa2, pa3, cvt_tf32(v10.x), cvt_tf32(v10.y), 0.f, 0.f, 0.f, 0.f);
            mma8(p0, p1, p2, p3, pb0, pb1, pb2, pb3, cvt_tf32(v11.x), cvt_tf32(v11.y), p0, p1, p2, p3);

            // ---- t[d]: column sums over q (rows already weighted) ----
            float c0 = o0 + o2, c1 = o1 + o3, c2 = p0 + p2, c3 = p1 + p3;
            #pragma unroll
            for (int off = 4; off <= 16; off <<= 1) {
                c0 += __shfl_xor_sync(FULLM, c0, off);
                c1 += __shfl_xor_sync(FULLM, c1, off);
                c2 += __shfl_xor_sync(FULLM, c2, off);
                c3 += __shfl_xor_sync(FULLM, c3, off);
            }

            // ---- z[c] per fg-group (partial dot; ez added ONCE after quad sum) ----
            float z = (fg < 7)
                ? fmaf(mz.x, c0, fmaf(mz.y, c1, fmaf(mz.z, c2, mz.w * c3)))
                : 0.f;
            z += __shfl_xor_sync(FULLM, z, 1);
            z += __shfl_xor_sync(FULLM, z, 2);
            float zq = (fg < 7) ? (z + ezv) : -1e30f;
            float zm = zq;
            zm = fmaxf(zm, __shfl_xor_sync(FULLM, zm, 4));
            zm = fmaxf(zm, __shfl_xor_sync(FULLM, zm, 8));
            zm = fmaxf(zm, __shfl_xor_sync(FULLM, zm, 16));
            float ex = __expf(zq - zm);
            float se = ex;
            se += __shfl_xor_sync(FULLM, se, 4);
            se += __shfl_xor_sync(FULLM, se, 8);
            se += __shfl_xor_sync(FULLM, se, 16);
            if (tg == 0 && fg < 7)
                out[samp * 7 + fg] = __fdividef(ex, se);
        }
    }
}

extern "C" void kernel_launch(void* const* d_in, const int* in_sizes, int n_in,
                              void* d_out, int out_size)
{
    const float* sample = (const float*)d_in[0];
    setup_kernel<<<1, 256>>>(
        (const float*)d_in[1],  (const float*)d_in[2],
        (const float*)d_in[3],  (const float*)d_in[4],
        (const float*)d_in[5],  (const float*)d_in[6],
        (const float*)d_in[7],  (const float*)d_in[8],
        (const float*)d_in[9],  (const float*)d_in[10],
        (const float*)d_in[11], (const float*)d_in[12],
        (const float*)d_in[13], (const float*)d_in[14],
        (const float*)d_in[15], (const float*)d_in[16],
        (const float*)d_in[17], (const float*)d_in[18]);

    const int nB = in_sizes[0] / 224;   // B = 131072
    hopfield_kernel<<<2048, 128>>>(sample, (float*)d_out, nB);
}

// round 6
// speedup vs baseline: 1.7295x; 1.2292x over previous
#include <cuda_runtime.h>

// ---------------------------------------------------------------------------
// M1_17008070492428: batched tiny Hopfield attention + classifier head.
//   B=131072 samples, each (S=14, D=16) -> (7,) softmax probs.
// R5 = R4 minus all cvt.rna.tf32: mma.sync tf32 reads the top bits of the
//   .b32 operand, so raw f32 bit patterns act as truncated tf32. Removes
//   ~40 ALU issues/sample and shortens the MMA->MMA dependency chains.
// Pipeline: PI-permuted QKV weights make each MMA C-fragment coincide with
// the next MMA's A/B fragment layout; Q,K,P stay in registers; V goes
// through a 16x24 smem transpose tile; everything else is shuffles.
// ---------------------------------------------------------------------------

typedef unsigned int u32;
#define LN_EPS 1e-5f
#define FULLM 0xffffffffu

__device__ __forceinline__ u32 f2t(float x) {          // f32 bits as tf32
    return __float_as_uint(x);
}
__device__ __forceinline__ void mma8(float& d0, float& d1, float& d2, float& d3,
                                     u32 a0, u32 a1, u32 a2, u32 a3,
                                     u32 b0, u32 b1,
                                     float c0, float c1, float c2, float c3) {
    asm("mma.sync.aligned.m16n8k8.row.col.f32.tf32.tf32.f32 "
        "{%0,%1,%2,%3},{%4,%5,%6,%7},{%8,%9},{%10,%11,%12,%13};"
        : "=f"(d0), "=f"(d1), "=f"(d2), "=f"(d3)
        : "r"(a0), "r"(a1), "r"(a2), "r"(a3), "r"(b0), "r"(b1),
          "f"(c0), "f"(c1), "f"(c2), "f"(c3));
}

struct __align__(16) Params {
    float wq[16][16], wk[16][16], wv[16][16];  // PI-permuted rows, LN-gamma folded
    float bq[16], bk[16], bv[16];              // PI-permuted, LN-beta folded
    float M[7][16];                            // Wb @ Wo (true-d columns)
    float ez[8];
    float wm[16];                              // Wm padded with zeros
};
__device__ Params g_P;

__global__ void setup_kernel(
    const float* __restrict__ lnqg, const float* __restrict__ lnqb,
    const float* __restrict__ lnkg, const float* __restrict__ lnkb,
    const float* __restrict__ lnvg, const float* __restrict__ lnvb,
    const float* __restrict__ Wq,  const float* __restrict__ bq,
    const float* __restrict__ Wk,  const float* __restrict__ bk,
    const float* __restrict__ Wv,  const float* __restrict__ bv,
    const float* __restrict__ Wo,  const float* __restrict__ bo,
    const float* __restrict__ Wm,  const float* __restrict__ bm,
    const float* __restrict__ Wb,  const float* __restrict__ bb)
{
    const int PI[16] = {0,4,1,5,2,6,3,7, 8,12,9,13,10,14,11,15};
    const int t = threadIdx.x;           // 256 threads, 1 block
    const int e = t >> 4, d = t & 15;
    const int pe = PI[e];
    g_P.wq[e][d] = Wq[pe * 16 + d] * lnqg[d];
    g_P.wk[e][d] = Wk[pe * 16 + d] * lnkg[d];
    g_P.wv[e][d] = Wv[pe * 16 + d] * lnvg[d];
    if (t < 16) {
        const int p = PI[t];
        float aq = bq[p], ak = bk[p], av = bv[p];
        #pragma unroll
        for (int i = 0; i < 16; i++) {
            aq = fmaf(lnqb[i], Wq[p * 16 + i], aq);
            ak = fmaf(lnkb[i], Wk[p * 16 + i], ak);
            av = fmaf(lnvb[i], Wv[p * 16 + i], av);
        }
        g_P.bq[t] = aq; g_P.bk[t] = ak; g_P.bv[t] = av;
        g_P.wm[t] = (t < 14) ? Wm[t] : 0.f;
    }
    if (t < 112) {
        const int c = t >> 4, dd = t & 15;
        float s = 0.f;
        for (int o = 0; o < 128; o++)
            s = fmaf(Wb[c * 128 + o], Wo[o * 16 + dd], s);
        g_P.M[c][dd] = s;
    }
    if (t >= 112 && t < 119) {
        const int c = t - 112;
        float c0 = 0.f;
        for (int s = 0; s < 14; s++) c0 += Wm[s];
        float z = bb[c];
        const float bmv = bm[0];
        for (int o = 0; o < 128; o++)
            z = fmaf(Wb[c * 128 + o], fmaf(c0, bo[o], bmv), z);
        g_P.ez[c] = z;
    }
    if (t == 119) g_P.ez[7] = 0.f;
}

__global__ __launch_bounds__(128, 4) void hopfield_kernel(
    const float* __restrict__ x, float* __restrict__ out, int nB)
{
    __shared__ __align__(16) float smVt[4][2][16 * 24];   // 12 KB
    const int tid  = threadIdx.x;
    const int lane = tid & 31;
    const int wid  = tid >> 5;
    const int fg   = lane >> 2;     // 0..7  (row group / B n-col)
    const int tg   = lane & 3;      // 0..3  (thread-in-quad)

    // ---- persistent weight B-fragments (raw f32 = truncated tf32) ----
    u32   bw[3][2][2][2];           // [proj][ntile][kstep][reg]
    float bs[3][2][2];
    {
        const float* Wp[3] = { &g_P.wq[0][0], &g_P.wk[0][0], &g_P.wv[0][0] };
        const float* Bp[3] = { g_P.bq, g_P.bk, g_P.bv };
        #pragma unroll
        for (int p = 0; p < 3; p++) {
            #pragma unroll
            for (int nt = 0; nt < 2; nt++) {
                #pragma unroll
                for (int ks = 0; ks < 2; ks++) {
                    const float* base = Wp[p] + (fg + 8 * nt) * 16 + 8 * ks;
                    bw[p][nt][ks][0] = f2t(__ldg(base + tg));
                    bw[p][nt][ks][1] = f2t(__ldg(base + tg + 4));
                }
                bs[p][nt][0] = __ldg(Bp[p] + 2 * tg + 8 * nt);
                bs[p][nt][1] = __ldg(Bp[p] + 2 * tg + 8 * nt + 1);
            }
        }
    }
    const float wmLo = g_P.wm[fg];
    const float wmHi = g_P.wm[fg + 8];      // 0 for rows 14,15
    float4 mz = make_float4(0.f, 0.f, 0.f, 0.f);
    float ezv = 0.f;
    if (fg < 7) {
        float2 a = *(const float2*)&g_P.M[fg][2 * tg];
        float2 b = *(const float2*)&g_P.M[fg][8 + 2 * tg];
        mz = make_float4(a.x, a.y, b.x, b.y);
        ezv = g_P.ez[fg];
    }

    const int totalWarps = gridDim.x * 4;
    for (int s0 = (blockIdx.x * 4 + wid) * 2; s0 < nB; s0 += totalWarps * 2) {
        #pragma unroll
        for (int smp = 0; smp < 2; smp++) {
            const int samp = s0 + smp;
            float* Vt = smVt[wid][smp];
            const float* xs = x + (long long)samp * 224;

            // ---- load x directly in fragment layout + LN via quad shuffles ----
            float xlo[4], xhi[4];
            #pragma unroll
            for (int u = 0; u < 4; u++) {
                xlo[u] = __ldg(xs + fg * 16 + tg + 4 * u);
                xhi[u] = (fg < 6) ? __ldg(xs + (fg + 8) * 16 + tg + 4 * u) : 0.f;
            }
            float s1l = ((xlo[0] + xlo[1]) + (xlo[2] + xlo[3]));
            float s2l = xlo[0] * xlo[0];
            s2l = fmaf(xlo[1], xlo[1], s2l); s2l = fmaf(xlo[2], xlo[2], s2l); s2l = fmaf(xlo[3], xlo[3], s2l);
            float s1h = ((xhi[0] + xhi[1]) + (xhi[2] + xhi[3]));
            float s2h = xhi[0] * xhi[0];
            s2h = fmaf(xhi[1], xhi[1], s2h); s2h = fmaf(xhi[2], xhi[2], s2h); s2h = fmaf(xhi[3], xhi[3], s2h);
            s1l += __shfl_xor_sync(FULLM, s1l, 1); s1l += __shfl_xor_sync(FULLM, s1l, 2);
            s2l += __shfl_xor_sync(FULLM, s2l, 1); s2l += __shfl_xor_sync(FULLM, s2l, 2);
            s1h += __shfl_xor_sync(FULLM, s1h, 1); s1h += __shfl_xor_sync(FULLM, s1h, 2);
            s2h += __shfl_xor_sync(FULLM, s2h, 1); s2h += __shfl_xor_sync(FULLM, s2h, 2);
            const float mL = s1l * 0.0625f;
            const float rL = rsqrtf(fmaf(-mL, mL, s2l * 0.0625f) + LN_EPS);
            const float mH = s1h * 0.0625f;
            const float rH = rsqrtf(fmaf(-mH, mH, s2h * 0.0625f) + LN_EPS);
            u32 a0 = f2t((xlo[0] - mL) * rL), a1 = f2t((xhi[0] - mH) * rH);
            u32 a2 = f2t((xlo[1] - mL) * rL), a3 = f2t((xhi[1] - mH) * rH);
            u32 a4 = f2t((xlo[2] - mL) * rL), a5 = f2t((xhi[2] - mH) * rH);
            u32 a6 = f2t((xlo[3] - mL) * rL), a7 = f2t((xhi[3] - mH) * rH);

            // ---- QKV (PI-permuted): C-frags land in true-d layout ----
            float Q[8], K[8], V[8];
            #pragma unroll
            for (int p = 0; p < 3; p++) {
                float* D = (p == 0) ? Q : ((p == 1) ? K : V);
                #pragma unroll
                for (int nt = 0; nt < 2; nt++) {
                    float d0, d1, d2, d3;
                    mma8(d0, d1, d2, d3, a0, a1, a2, a3,
                         bw[p][nt][0][0], bw[p][nt][0][1],
                         bs[p][nt][0], bs[p][nt][1], bs[p][nt][0], bs[p][nt][1]);
                    mma8(d0, d1, d2, d3, a4, a5, a6, a7,
                         bw[p][nt][1][0], bw[p][nt][1][1], d0, d1, d2, d3);
                    D[nt * 4 + 0] = d0; D[nt * 4 + 1] = d1;
                    D[nt * 4 + 2] = d2; D[nt * 4 + 3] = d3;
                }
            }

            // ---- stage V transposed: Vt[d][key], stride 24 (conflict-free) ----
            Vt[ tg       * 24 + fg    ] = V[0];
            Vt[(tg + 4)  * 24 + fg    ] = V[1];
            Vt[ tg       * 24 + fg + 8] = V[2];
            Vt[(tg + 4)  * 24 + fg + 8] = V[3];
            Vt[(tg + 8)  * 24 + fg    ] = V[4];
            Vt[(tg + 12) * 24 + fg    ] = V[5];
            Vt[(tg + 8)  * 24 + fg + 8] = V[6];
            Vt[(tg + 12) * 24 + fg + 8] = V[7];

            // ---- S = Q K^T : pure register MMA ----
            u32 qa0 = f2t(Q[0]), qa1 = f2t(Q[2]), qa2 = f2t(Q[1]), qa3 = f2t(Q[3]);
            u32 qa4 = f2t(Q[4]), qa5 = f2t(Q[6]), qa6 = f2t(Q[5]), qa7 = f2t(Q[7]);
            float t0, t1, t2, t3, u0, u1, u2, u3;
            mma8(t0, t1, t2, t3, qa0, qa1, qa2, qa3, f2t(K[0]), f2t(K[1]), 0.f, 0.f, 0.f, 0.f);
            mma8(t0, t1, t2, t3, qa4, qa5, qa6, qa7, f2t(K[4]), f2t(K[5]), t0, t1, t2, t3);
            mma8(u0, u1, u2, u3, qa0, qa1, qa2, qa3, f2t(K[2]), f2t(K[3]), 0.f, 0.f, 0.f, 0.f);
            mma8(u0, u1, u2, u3, qa4, qa5, qa6, qa7, f2t(K[6]), f2t(K[7]), u0, u1, u2, u3);
            if (tg == 3) { u0 = -1e30f; u1 = -1e30f; u2 = -1e30f; u3 = -1e30f; }  // keys 14,15

            // ---- softmax rows (quad shuffles), fold wm*inv into P ----
            float mLo = fmaxf(fmaxf(t0, t1), fmaxf(u0, u1));
            mLo = fmaxf(mLo, __shfl_xor_sync(FULLM, mLo, 1));
            mLo = fmaxf(mLo, __shfl_xor_sync(FULLM, mLo, 2));
            float mHi = fmaxf(fmaxf(t2, t3), fmaxf(u2, u3));
            mHi = fmaxf(mHi, __shfl_xor_sync(FULLM, mHi, 1));
            mHi = fmaxf(mHi, __shfl_xor_sync(FULLM, mHi, 2));
            float e0 = __expf(t0 - mLo), e1 = __expf(t1 - mLo), e4 = __expf(u0 - mLo), e5 = __expf(u1 - mLo);
            float e2 = __expf(t2 - mHi), e3 = __expf(t3 - mHi), e6 = __expf(u2 - mHi), e7 = __expf(u3 - mHi);
            float sl = (e0 + e1) + (e4 + e5);
            sl += __shfl_xor_sync(FULLM, sl, 1); sl += __shfl_xor_sync(FULLM, sl, 2);
            float sh = (e2 + e3) + (e6 + e7);
            sh += __shfl_xor_sync(FULLM, sh, 1); sh += __shfl_xor_sync(FULLM, sh, 2);
            const float wl = wmLo * __fdividef(1.f, sl);
            const float wh = wmHi * __fdividef(1.f, sh);
            u32 pa0 = f2t(e0 * wl), pa1 = f2t(e2 * wh), pa2 = f2t(e1 * wl), pa3 = f2t(e3 * wh);
            u32 pb0 = f2t(e4 * wl), pb1 = f2t(e6 * wh), pb2 = f2t(e5 * wl), pb3 = f2t(e7 * wh);

            __syncwarp();
            const float2 v00 = *(const float2*)&Vt[fg * 24 + 2 * tg];
            const float2 v01 = *(const float2*)&Vt[fg * 24 + 8 + 2 * tg];
            const float2 v10 = *(const float2*)&Vt[(fg + 8) * 24 + 2 * tg];
            const float2 v11 = *(const float2*)&Vt[(fg + 8) * 24 + 8 + 2 * tg];

            // ---- O = P' V (key dim permuted consistently on both sides) ----
            float o0, o1, o2, o3, p0, p1, p2, p3;
            mma8(o0, o1, o2, o3, pa0, pa1, pa2, pa3, f2t(v00.x), f2t(v00.y), 0.f, 0.f, 0.f, 0.f);
            mma8(o0, o1, o2, o3, pb0, pb1, pb2, pb3, f2t(v01.x), f2t(v01.y), o0, o1, o2, o3);
            mma8(p0, p1, p2, p3, pa0, pa1, pa2, pa3, f2t(v10.x), f2t(v10.y), 0.f, 0.f, 0.f, 0.f);
            mma8(p0, p1, p2, p3, pb0, pb1, pb2, pb3, f2t(v11.x), f2t(v11.y), p0, p1, p2, p3);

            // ---- t[d]: column sums over q (rows already weighted) ----
            float c0 = o0 + o2, c1 = o1 + o3, c2 = p0 + p2, c3 = p1 + p3;
            #pragma unroll
            for (int off = 4; off <= 16; off <<= 1) {
                c0 += __shfl_xor_sync(FULLM, c0, off);
                c1 += __shfl_xor_sync(FULLM, c1, off);
                c2 += __shfl_xor_sync(FULLM, c2, off);
                c3 += __shfl_xor_sync(FULLM, c3, off);
            }

            // ---- z[c] per fg-group (partial dot; ez added ONCE after quad sum) ----
            float z = (fg < 7)
                ? fmaf(mz.x, c0, fmaf(mz.y, c1, fmaf(mz.z, c2, mz.w * c3)))
                : 0.f;
            z += __shfl_xor_sync(FULLM, z, 1);
            z += __shfl_xor_sync(FULLM, z, 2);
            float zq = (fg < 7) ? (z + ezv) : -1e30f;
            float zm = zq;
            zm = fmaxf(zm, __shfl_xor_sync(FULLM, zm, 4));
            zm = fmaxf(zm, __shfl_xor_sync(FULLM, zm, 8));
            zm = fmaxf(zm, __shfl_xor_sync(FULLM, zm, 16));
            float ex = __expf(zq - zm);
            float se = ex;
            se += __shfl_xor_sync(FULLM, se, 4);
            se += __shfl_xor_sync(FULLM, se, 8);
            se += __shfl_xor_sync(FULLM, se, 16);
            if (tg == 0 && fg < 7)
                out[samp * 7 + fg] = __fdividef(ex, se);
        }
    }
}

extern "C" void kernel_launch(void* const* d_in, const int* in_sizes, int n_in,
                              void* d_out, int out_size)
{
    const float* sample = (const float*)d_in[0];
    setup_kernel<<<1, 256>>>(
        (const float*)d_in[1],  (const float*)d_in[2],
        (const float*)d_in[3],  (const float*)d_in[4],
        (const float*)d_in[5],  (const float*)d_in[6],
        (const float*)d_in[7],  (const float*)d_in[8],
        (const float*)d_in[9],  (const float*)d_in[10],
        (const float*)d_in[11], (const float*)d_in[12],
        (const float*)d_in[13], (const float*)d_in[14],
        (const float*)d_in[15], (const float*)d_in[16],
        (const float*)d_in[17], (const float*)d_in[18]);

    const int nB = in_sizes[0] / 224;   // B = 131072
    hopfield_kernel<<<2048, 128>>>(sample, (float*)d_out, nB);
}